// round 2
// baseline (speedup 1.0000x reference)
#include <cuda_runtime.h>
#include <cstdint>
#include <cstddef>

#define BDIM   512
#define CELL   768
#define RANK   64
#define DF     256
#define KDNA   4000
#define NW     98304
#define HALF   49152
#define KSPLIT1 10

// ---------------- device scratch (module-load allocated, allowed) ----------------
__device__ float g_part[KSPLIT1 * BDIM * DF];        // GEMM1 split-K partials (5.2 MB)
__device__ float g_h[BDIM * DF];                     // relu(dna)  (512x256)
__device__ float g_w[(size_t)BDIM * NW];             // weights    (512x98304, 201 MB)
__device__ float g_t[BDIM * RANK];                   // t = V^T x  (512x64)

// ---------------- generic 128x128x8 SGEMM, 256 threads, 8x8 microtile ----------
// C[M,N] = A[M,K] @ B[K,N].  gridDim.z = K-slices; if applyBiasRelu==0 the slice
// writes its partial to C + slice*M*N; else (single slice) bias (+relu) applied.
__global__ void __launch_bounds__(256, 2)
sgemm_k(const float* __restrict__ A, const float* __restrict__ Bmat,
        const float* __restrict__ bias, float* __restrict__ C,
        int M, int N, int K, int applyBiasRelu)
{
    const int bn = blockIdx.x;            // N tile index
    const int bm = blockIdx.y;            // M tile index
    const int slice = blockIdx.z;
    const int nslices = gridDim.z;
    const int kPer = K / nslices;
    const int k0base = slice * kPer;

    __shared__ float As[8][128];          // transposed A tile
    __shared__ float Bs[8][128];

    const int tid = threadIdx.x;
    const int aRow = tid >> 1;            // 0..127
    const int aK4  = (tid & 1) * 4;       // 0 or 4
    const int bK   = tid >> 5;            // 0..7
    const int bN4  = (tid & 31) * 4;      // 0..124

    const int tx = tid & 15;              // n-dir thread coord
    const int ty = tid >> 4;              // m-dir thread coord

    float acc[8][8];
    #pragma unroll
    for (int i = 0; i < 8; i++)
        #pragma unroll
        for (int j = 0; j < 8; j++) acc[i][j] = 0.f;

    const float* Aptr = A + (size_t)(bm * 128 + aRow) * K + k0base + aK4;
    const float* Bptr = Bmat + (size_t)(k0base + bK) * N + (size_t)bn * 128 + bN4;

    const int nsteps = kPer / 8;
    for (int kt = 0; kt < nsteps; kt++) {
        float4 av = *(const float4*)(Aptr);
        float4 bv = *(const float4*)(Bptr);
        As[aK4 + 0][aRow] = av.x;
        As[aK4 + 1][aRow] = av.y;
        As[aK4 + 2][aRow] = av.z;
        As[aK4 + 3][aRow] = av.w;
        *(float4*)&Bs[bK][bN4] = bv;
        __syncthreads();
        #pragma unroll
        for (int k = 0; k < 8; k++) {
            float af[8], bf[8];
            #pragma unroll
            for (int i = 0; i < 8; i++) af[i] = As[k][ty * 8 + i];
            #pragma unroll
            for (int j = 0; j < 8; j++) bf[j] = Bs[k][tx * 8 + j];
            #pragma unroll
            for (int i = 0; i < 8; i++)
                #pragma unroll
                for (int j = 0; j < 8; j++)
                    acc[i][j] += af[i] * bf[j];
        }
        __syncthreads();
        Aptr += 8;
        Bptr += (size_t)8 * N;
    }

    float* Cbase = C + (size_t)slice * M * N;
    #pragma unroll
    for (int i = 0; i < 8; i++) {
        const int row = bm * 128 + ty * 8 + i;
        #pragma unroll
        for (int j = 0; j < 8; j += 4) {
            const int col = bn * 128 + tx * 8 + j;
            float4 v = make_float4(acc[i][j], acc[i][j + 1], acc[i][j + 2], acc[i][j + 3]);
            if (applyBiasRelu) {
                v.x += bias[col];     v.y += bias[col + 1];
                v.z += bias[col + 2]; v.w += bias[col + 3];
                if (applyBiasRelu == 2) {
                    v.x = fmaxf(v.x, 0.f); v.y = fmaxf(v.y, 0.f);
                    v.z = fmaxf(v.z, 0.f); v.w = fmaxf(v.w, 0.f);
                }
            }
            *(float4*)(Cbase + (size_t)row * N + col) = v;
        }
    }
}

// ---------------- reduce split-K partials + bias + relu (GEMM1 epilogue) --------
__global__ void reduce_relu_k(const float* __restrict__ part,
                              const float* __restrict__ bias,
                              float* __restrict__ out)
{
    const int i = blockIdx.x * 256 + threadIdx.x;   // i < 512*256
    float s = bias[i & (DF - 1)];
    #pragma unroll
    for (int sl = 0; sl < KSPLIT1; sl++) s += part[sl * (BDIM * DF) + i];
    out[i] = fmaxf(s, 0.f);
}

// ---------------- t[b,r] = sum_j V[b,j,r] * x[b,j] ------------------------------
__global__ void compute_t_k(const float* __restrict__ w, const float* __restrict__ x,
                            float* __restrict__ t)
{
    const int b = blockIdx.x;
    const int tid = threadIdx.x;         // 256
    const int r = tid & 63;
    const int jg = tid >> 6;             // 0..3
    __shared__ float sx[CELL];
    for (int j = tid; j < CELL; j += 256) sx[j] = x[(size_t)b * CELL + j];
    __syncthreads();
    const float* wb = w + (size_t)b * NW + HALF;
    float acc = 0.f;
    for (int j = jg; j < CELL; j += 4)
        acc += wb[j * 64 + r] * sx[j];
    __shared__ float red[256];
    red[tid] = acc;
    __syncthreads();
    if (tid < 64)
        t[b * RANK + tid] = red[tid] + red[64 + tid] + red[128 + tid] + red[192 + tid];
}

// ---------------- pred[b,i] = sum_r U[b,i,r] * t[b,r] ---------------------------
__global__ void compute_pred_k(const float* __restrict__ w, const float* __restrict__ t,
                               float* __restrict__ out)
{
    const int b = blockIdx.y;
    const int i = blockIdx.x * 256 + threadIdx.x;   // i < 768
    __shared__ float st[RANK];
    if (threadIdx.x < RANK) st[threadIdx.x] = t[b * RANK + threadIdx.x];
    __syncthreads();
    const float4* wb = (const float4*)(w + (size_t)b * NW + (size_t)i * RANK);
    float acc = 0.f;
    #pragma unroll
    for (int r4 = 0; r4 < RANK / 4; r4++) {
        float4 v = wb[r4];
        acc += v.x * st[r4 * 4 + 0] + v.y * st[r4 * 4 + 1]
             + v.z * st[r4 * 4 + 2] + v.w * st[r4 * 4 + 3];
    }
    out[(size_t)b * CELL + i] = acc;
}

// ---------------- launch ---------------------------------------------------------
extern "C" void kernel_launch(void* const* d_in, const int* in_sizes, int n_in,
                              void* d_out, int out_size)
{
    const float* x     = (const float*)d_in[0];   // control_state (512,768)
    const float* seq   = (const float*)d_in[1];   // sequence_prob_matrix flat (512,4000)
    const float* W_dna = (const float*)d_in[2];   // (4000,256)
    const float* b_dna = (const float*)d_in[3];   // (256,)
    const float* W_hyp = (const float*)d_in[4];   // (256,98304)
    const float* b_hyp = (const float*)d_in[5];   // (98304,)
    float* out = (float*)d_out;                   // (512,768)

    float *p_part, *p_h, *p_w, *p_t;
    cudaGetSymbolAddress((void**)&p_part, g_part);
    cudaGetSymbolAddress((void**)&p_h,    g_h);
    cudaGetSymbolAddress((void**)&p_w,    g_w);
    cudaGetSymbolAddress((void**)&p_t,    g_t);

    // GEMM1: (512 x 4000) @ (4000 x 256), split-K=10 -> partials
    {
        dim3 grid(DF / 128, BDIM / 128, KSPLIT1);   // (2,4,10)
        sgemm_k<<<grid, 256>>>(seq, W_dna, nullptr, p_part, BDIM, DF, KDNA, 0);
    }
    // reduce partials + bias + relu -> g_h
    reduce_relu_k<<<(BDIM * DF) / 256, 256>>>(p_part, b_dna, p_h);

    // GEMM2: (512 x 256) @ (256 x 98304) + bias -> g_w
    {
        dim3 grid(NW / 128, BDIM / 128, 1);         // (768,4,1)
        sgemm_k<<<grid, 256>>>(p_h, W_hyp, b_hyp, p_w, BDIM, NW, DF, 1);
    }

    // t = V^T x
    compute_t_k<<<BDIM, 256>>>(p_w, x, p_t);

    // pred = U t
    {
        dim3 grid(CELL / 256, BDIM);                // (3,512)
        compute_pred_k<<<grid, 256>>>(p_w, p_t, out);
    }
}

// round 5
// speedup vs baseline: 2.1069x; 2.1069x over previous
#include <cuda_runtime.h>
#include <cuda_bf16.h>
#include <cstdint>
#include <cstddef>

#define BDIM   512
#define CELL   768
#define RANK   64
#define DF     256
#define KDNA   4000
#define NW     98304
#define HALF   49152
#define KSPLIT1 10

// ---------------------------------------------------------------------------
// warp-level mma helpers (sm_100 family-safe: mma.sync + ldmatrix)
// ---------------------------------------------------------------------------
__device__ __forceinline__ void mma_bf16(float c[4],
                                         uint32_t a0, uint32_t a1, uint32_t a2, uint32_t a3,
                                         uint32_t b0, uint32_t b1)
{
    asm volatile(
        "mma.sync.aligned.m16n8k16.row.col.f32.bf16.bf16.f32 "
        "{%0,%1,%2,%3}, {%4,%5,%6,%7}, {%8,%9}, {%0,%1,%2,%3};"
        : "+f"(c[0]), "+f"(c[1]), "+f"(c[2]), "+f"(c[3])
        : "r"(a0), "r"(a1), "r"(a2), "r"(a3), "r"(b0), "r"(b1));
}
__device__ __forceinline__ uint32_t smem_u32(const void* p) {
    uint32_t a;
    asm("{ .reg .u64 t; cvta.to.shared.u64 t, %1; cvt.u32.u64 %0, t; }" : "=r"(a) : "l"(p));
    return a;
}
#define LDMX4(r0, r1, r2, r3, addr) \
    asm volatile("ldmatrix.sync.aligned.m8n8.x4.shared.b16 {%0,%1,%2,%3}, [%4];" \
                 : "=r"(r0), "=r"(r1), "=r"(r2), "=r"(r3) : "r"(addr))
#define LDMX2(r0, r1, addr) \
    asm volatile("ldmatrix.sync.aligned.m8n8.x2.shared.b16 {%0,%1}, [%2];" \
                 : "=r"(r0), "=r"(r1) : "r"(addr))

// ---------------------------------------------------------------------------
// device scratch
// ---------------------------------------------------------------------------
__device__ float g_part[KSPLIT1 * BDIM * DF];
__device__ __align__(256) __nv_bfloat16 g_Ah[BDIM * DF];
__device__ __align__(256) __nv_bfloat16 g_Al[BDIM * DF];
__device__ __align__(256) __nv_bfloat16 g_Bh[(size_t)NW * DF];   // W_hyper^T hi [n][k]
__device__ __align__(256) __nv_bfloat16 g_Bl[(size_t)NW * DF];   // lo
__device__ float g_v[(size_t)BDIM * HALF];                        // V half (+bias)
__device__ float g_t[BDIM * RANK];

// ---------------------------------------------------------------------------
// GEMM1: SIMT 128x128x8 SGEMM, split-K partials
// ---------------------------------------------------------------------------
__global__ void __launch_bounds__(256, 2)
sgemm_k(const float* __restrict__ A, const float* __restrict__ Bmat,
        float* __restrict__ C, int M, int N, int K)
{
    const int bn = blockIdx.x, bm = blockIdx.y, slice = blockIdx.z;
    const int kPer = K / gridDim.z;
    const int k0base = slice * kPer;

    __shared__ float As[8][128];
    __shared__ float Bs[8][128];

    const int tid = threadIdx.x;
    const int aRow = tid >> 1, aK4 = (tid & 1) * 4;
    const int bK = tid >> 5, bN4 = (tid & 31) * 4;
    const int tx = tid & 15, ty = tid >> 4;

    float acc[8][8];
    #pragma unroll
    for (int i = 0; i < 8; i++)
        #pragma unroll
        for (int j = 0; j < 8; j++) acc[i][j] = 0.f;

    const float* Aptr = A + (size_t)(bm * 128 + aRow) * K + k0base + aK4;
    const float* Bptr = Bmat + (size_t)(k0base + bK) * N + (size_t)bn * 128 + bN4;

    const int nsteps = kPer / 8;
    for (int kt = 0; kt < nsteps; kt++) {
        float4 av = *(const float4*)(Aptr);
        float4 bv = *(const float4*)(Bptr);
        As[aK4 + 0][aRow] = av.x; As[aK4 + 1][aRow] = av.y;
        As[aK4 + 2][aRow] = av.z; As[aK4 + 3][aRow] = av.w;
        *(float4*)&Bs[bK][bN4] = bv;
        __syncthreads();
        #pragma unroll
        for (int k = 0; k < 8; k++) {
            float af[8], bf[8];
            #pragma unroll
            for (int i = 0; i < 8; i++) af[i] = As[k][ty * 8 + i];
            #pragma unroll
            for (int j = 0; j < 8; j++) bf[j] = Bs[k][tx * 8 + j];
            #pragma unroll
            for (int i = 0; i < 8; i++)
                #pragma unroll
                for (int j = 0; j < 8; j++) acc[i][j] += af[i] * bf[j];
        }
        __syncthreads();
        Aptr += 8;
        Bptr += (size_t)8 * N;
    }
    float* Cbase = C + (size_t)slice * M * N;
    #pragma unroll
    for (int i = 0; i < 8; i++) {
        const int row = bm * 128 + ty * 8 + i;
        #pragma unroll
        for (int j = 0; j < 8; j += 4) {
            const int col = bn * 128 + tx * 8 + j;
            float4 v = make_float4(acc[i][j], acc[i][j+1], acc[i][j+2], acc[i][j+3]);
            *(float4*)(Cbase + (size_t)row * N + col) = v;
        }
    }
}

// ---------------------------------------------------------------------------
// reduce split-K + bias + relu -> bf16 hi/lo split
// ---------------------------------------------------------------------------
__global__ void reduce_relu_convert_k(const float* __restrict__ part,
                                      const float* __restrict__ bias,
                                      __nv_bfloat16* __restrict__ Ah,
                                      __nv_bfloat16* __restrict__ Al)
{
    const int i = blockIdx.x * 256 + threadIdx.x;
    float s = bias[i & (DF - 1)];
    #pragma unroll
    for (int sl = 0; sl < KSPLIT1; sl++) s += part[sl * (BDIM * DF) + i];
    s = fmaxf(s, 0.f);
    __nv_bfloat16 h = __float2bfloat16(s);
    Ah[i] = h;
    Al[i] = __float2bfloat16(s - __bfloat162float(h));
}

// ---------------------------------------------------------------------------
// W_hyper [256, 98304] fp32 -> transposed bf16 hi/lo [98304, 256]
// ---------------------------------------------------------------------------
__global__ void __launch_bounds__(256)
transpose_convert_k(const float* __restrict__ W,
                    __nv_bfloat16* __restrict__ Bh, __nv_bfloat16* __restrict__ Bl)
{
    __shared__ float s[64][65];
    const int n0 = blockIdx.x * 64, k0 = blockIdx.y * 64;
    const int t = threadIdx.x;
    {
        const int nn = t & 63, kk = t >> 6;
        #pragma unroll
        for (int p = 0; p < 16; p++) {
            int k = kk + p * 4;
            s[k][nn] = W[(size_t)(k0 + k) * NW + n0 + nn];
        }
    }
    __syncthreads();
    const int n = t >> 2, su = (t & 3) * 16;
    __align__(16) __nv_bfloat16 hi[16];
    __align__(16) __nv_bfloat16 lo[16];
    #pragma unroll
    for (int i = 0; i < 16; i++) {
        float v = s[su + i][n];
        __nv_bfloat16 h = __float2bfloat16(v);
        hi[i] = h;
        lo[i] = __float2bfloat16(v - __bfloat162float(h));
    }
    const size_t o = (size_t)(n0 + n) * DF + k0 + su;
    *(int4*)(Bh + o)     = *(int4*)hi;
    *(int4*)(Bh + o + 8) = *(int4*)(hi + 8);
    *(int4*)(Bl + o)     = *(int4*)lo;
    *(int4*)(Bl + o + 8) = *(int4*)(lo + 8);
}

// ---------------------------------------------------------------------------
// mma.sync GEMM: C[128m x 128n] = A[128,256] @ B[128,256]^T, bf16x3.
// V mode (pred==nullptr): writes C+bias to vout (cols nrow0-HALF..).
// U mode: contracts (C+bias) with t -> pred directly.
// ---------------------------------------------------------------------------
#define LDSTR 72                         // smem stride (bf16) -> conflict-free
#define SM_AH 0
#define SM_AL (128 * LDSTR)
#define SM_BH (2 * 128 * LDSTR)
#define SM_BL (3 * 128 * LDSTR)
#define GEMM2_SMEM (4 * 128 * LDSTR * 2) // 73728 bytes

__device__ __forceinline__ void load_tile(__nv_bfloat16* dst,
                                          const __nv_bfloat16* __restrict__ src,
                                          int tid)
{
    // 128 rows x 64 k (one chunk); src row stride = DF
    #pragma unroll
    for (int p = 0; p < 4; p++) {
        const int u = tid + p * 256;
        const int row = u >> 3, j = u & 7;
        *(int4*)&dst[row * LDSTR + j * 8] =
            *(const int4*)&src[(size_t)row * DF + j * 8];
    }
}

__global__ void __launch_bounds__(256)
gemm_mma_k(const __nv_bfloat16* __restrict__ Ahg, const __nv_bfloat16* __restrict__ Alg,
           const __nv_bfloat16* __restrict__ Bhg, const __nv_bfloat16* __restrict__ Blg,
           const float* __restrict__ bias, const float* __restrict__ tvec,
           float* __restrict__ vout, float* __restrict__ pred, int ntile0)
{
    extern __shared__ __nv_bfloat16 sm[];
    const int tid = threadIdx.x, wid = tid >> 5, lane = tid & 31;
    const int bm = blockIdx.x;                 // fast dim -> B tile L2 reuse
    const int ntile = ntile0 + blockIdx.y;
    const int m0 = bm * 128, nrow0 = ntile * 128;
    const int warp_m = wid & 1, warp_n = wid >> 1;
    const int g = lane >> 2, t4 = lane & 3;

    float acc[4][4][4];
    #pragma unroll
    for (int mf = 0; mf < 4; mf++)
        #pragma unroll
        for (int nf = 0; nf < 4; nf++)
            #pragma unroll
            for (int c = 0; c < 4; c++) acc[mf][nf][c] = 0.f;

    // ldmatrix lane-address components (element offsets; *2 for bytes)
    const int a_row = warp_m * 64 + (lane & 15);       // + mf*16
    const int a_koff = (lane >> 4) * 8;                // + ks*16
    const int b_row = warp_n * 32 + (lane & 7);        // + nf*8
    const int b_koff = ((lane >> 3) & 1) * 8;          // + ks*16
    const uint32_t sb = smem_u32(sm);

    const __nv_bfloat16* Asrc_h = Ahg + (size_t)m0 * DF;
    const __nv_bfloat16* Asrc_l = Alg + (size_t)m0 * DF;
    const __nv_bfloat16* Bsrc_h = Bhg + (size_t)nrow0 * DF;
    const __nv_bfloat16* Bsrc_l = Blg + (size_t)nrow0 * DF;

    for (int kc = 0; kc < 4; kc++) {
        const int k0 = kc * 64;
        __syncthreads();
        load_tile(sm + SM_AH, Asrc_h + k0, tid);
        load_tile(sm + SM_AL, Asrc_l + k0, tid);
        load_tile(sm + SM_BH, Bsrc_h + k0, tid);
        load_tile(sm + SM_BL, Bsrc_l + k0, tid);
        __syncthreads();

        #pragma unroll
        for (int ks = 0; ks < 4; ks++) {
            uint32_t ah[4][4], al[4][4];
            #pragma unroll
            for (int mf = 0; mf < 4; mf++) {
                uint32_t adrh = sb + (uint32_t)(SM_AH + (a_row + mf * 16) * LDSTR + ks * 16 + a_koff) * 2;
                LDMX4(ah[mf][0], ah[mf][1], ah[mf][2], ah[mf][3], adrh);
                uint32_t adrl = sb + (uint32_t)(SM_AL + (a_row + mf * 16) * LDSTR + ks * 16 + a_koff) * 2;
                LDMX4(al[mf][0], al[mf][1], al[mf][2], al[mf][3], adrl);
            }
            #pragma unroll
            for (int nf = 0; nf < 4; nf++) {
                uint32_t bh0, bh1, bl0, bl1;
                uint32_t bdrh = sb + (uint32_t)(SM_BH + (b_row + nf * 8) * LDSTR + ks * 16 + b_koff) * 2;
                LDMX2(bh0, bh1, bdrh);
                uint32_t bdrl = sb + (uint32_t)(SM_BL + (b_row + nf * 8) * LDSTR + ks * 16 + b_koff) * 2;
                LDMX2(bl0, bl1, bdrl);
                #pragma unroll
                for (int mf = 0; mf < 4; mf++)
                    mma_bf16(acc[mf][nf], ah[mf][0], ah[mf][1], ah[mf][2], ah[mf][3], bh0, bh1);
                #pragma unroll
                for (int mf = 0; mf < 4; mf++)
                    mma_bf16(acc[mf][nf], ah[mf][0], ah[mf][1], ah[mf][2], ah[mf][3], bl0, bl1);
                #pragma unroll
                for (int mf = 0; mf < 4; mf++)
                    mma_bf16(acc[mf][nf], al[mf][0], al[mf][1], al[mf][2], al[mf][3], bh0, bh1);
            }
        }
    }

    // ------------------------- epilogue -------------------------
    if (pred == nullptr) {
        // V mode: direct stores of C + bias
        #pragma unroll
        for (int mf = 0; mf < 4; mf++) {
            const int row = warp_m * 64 + mf * 16 + g;
            #pragma unroll
            for (int nf = 0; nf < 4; nf++) {
                const int col = warp_n * 32 + nf * 8 + 2 * t4;
                const float b0 = bias[nrow0 + col], b1 = bias[nrow0 + col + 1];
                const size_t base = (size_t)(m0 + row) * HALF + (nrow0 - HALF) + col;
                float2 v0 = make_float2(acc[mf][nf][0] + b0, acc[mf][nf][1] + b1);
                float2 v1 = make_float2(acc[mf][nf][2] + b0, acc[mf][nf][3] + b1);
                *(float2*)&vout[base] = v0;
                *(float2*)&vout[base + (size_t)8 * HALF] = v1;
            }
        }
    } else {
        // U mode: pred[b, i] = sum_col (C+bias) * t[b, col&63]
        __syncthreads();                    // all warps done reading smem tiles
        float* spart = (float*)sm;          // spart[row][4 warp_n slots]
        #pragma unroll
        for (int mf = 0; mf < 4; mf++) {
            const int row_lo = warp_m * 64 + mf * 16 + g;
            float p0 = 0.f, p1 = 0.f;
            #pragma unroll
            for (int nf = 0; nf < 4; nf++) {
                const int col = warp_n * 32 + nf * 8 + 2 * t4;
                const int r = col & 63;
                const float b0 = bias[nrow0 + col], b1 = bias[nrow0 + col + 1];
                const float* t0p = tvec + (size_t)(m0 + row_lo) * RANK;
                const float* t1p = tvec + (size_t)(m0 + row_lo + 8) * RANK;
                p0 += (acc[mf][nf][0] + b0) * t0p[r] + (acc[mf][nf][1] + b1) * t0p[r + 1];
                p1 += (acc[mf][nf][2] + b0) * t1p[r] + (acc[mf][nf][3] + b1) * t1p[r + 1];
            }
            p0 += __shfl_xor_sync(0xFFFFFFFF, p0, 1);
            p0 += __shfl_xor_sync(0xFFFFFFFF, p0, 2);
            p1 += __shfl_xor_sync(0xFFFFFFFF, p1, 1);
            p1 += __shfl_xor_sync(0xFFFFFFFF, p1, 2);
            if (t4 == 0) {
                spart[row_lo * 4 + warp_n] = p0;
                spart[(row_lo + 8) * 4 + warp_n] = p1;
            }
        }
        __syncthreads();
        // combine warp_n pairs -> pred
        {
            const int row = tid >> 1, ih = tid & 1;
            const float v = spart[row * 4 + 2 * ih] + spart[row * 4 + 2 * ih + 1];
            pred[(size_t)(m0 + row) * CELL + 2 * ntile + ih] = v;
        }
    }
}

// ---------------------------------------------------------------------------
// t[b,r] = sum_j V[b,j,r] * x[b,j]
// ---------------------------------------------------------------------------
__global__ void compute_t_k(const float* __restrict__ v, const float* __restrict__ x,
                            float* __restrict__ t)
{
    const int b = blockIdx.x;
    const int tid = threadIdx.x;
    const int r = tid & 63;
    const int jg = tid >> 6;
    __shared__ float sx[CELL];
    for (int j = tid; j < CELL; j += 256) sx[j] = x[(size_t)b * CELL + j];
    __syncthreads();
    const float* vb = v + (size_t)b * HALF;
    float acc = 0.f;
    for (int j = jg; j < CELL; j += 4)
        acc += vb[j * 64 + r] * sx[j];
    __shared__ float red[256];
    red[tid] = acc;
    __syncthreads();
    if (tid < 64)
        t[b * RANK + tid] = red[tid] + red[64 + tid] + red[128 + tid] + red[192 + tid];
}

// ---------------------------------------------------------------------------
// launch
// ---------------------------------------------------------------------------
extern "C" void kernel_launch(void* const* d_in, const int* in_sizes, int n_in,
                              void* d_out, int out_size)
{
    const float* x     = (const float*)d_in[0];
    const float* seq   = (const float*)d_in[1];
    const float* W_dna = (const float*)d_in[2];
    const float* b_dna = (const float*)d_in[3];
    const float* W_hyp = (const float*)d_in[4];
    const float* b_hyp = (const float*)d_in[5];
    float* out = (float*)d_out;

    float *p_part, *p_v, *p_t;
    __nv_bfloat16 *p_Ah, *p_Al, *p_Bh, *p_Bl;
    cudaGetSymbolAddress((void**)&p_part, g_part);
    cudaGetSymbolAddress((void**)&p_Ah, g_Ah);
    cudaGetSymbolAddress((void**)&p_Al, g_Al);
    cudaGetSymbolAddress((void**)&p_Bh, g_Bh);
    cudaGetSymbolAddress((void**)&p_Bl, g_Bl);
    cudaGetSymbolAddress((void**)&p_v, g_v);
    cudaGetSymbolAddress((void**)&p_t, g_t);

    cudaFuncSetAttribute(gemm_mma_k, cudaFuncAttributeMaxDynamicSharedMemorySize, GEMM2_SMEM);

    // W_hyper -> transposed bf16 hi/lo
    {
        dim3 grid(NW / 64, DF / 64);
        transpose_convert_k<<<grid, 256>>>(W_hyp, p_Bh, p_Bl);
    }
    // GEMM1 split-K + epilogue
    {
        dim3 grid(DF / 128, BDIM / 128, KSPLIT1);
        sgemm_k<<<grid, 256>>>(seq, W_dna, p_part, BDIM, DF, KDNA);
    }
    reduce_relu_convert_k<<<(BDIM * DF) / 256, 256>>>(p_part, b_dna, p_Ah, p_Al);

    // V-GEMM: n-tiles [384, 768) -> g_v (+bias)
    {
        dim3 grid(BDIM / 128, 384);
        gemm_mma_k<<<grid, 256, GEMM2_SMEM>>>(p_Ah, p_Al, p_Bh, p_Bl, b_hyp,
                                              nullptr, p_v, nullptr, 384);
    }
    // t = V^T x
    compute_t_k<<<BDIM, 256>>>(p_v, x, p_t);

    // U-GEMM: n-tiles [0, 384) fused with t-contraction -> out
    {
        dim3 grid(BDIM / 128, 384);
        gemm_mma_k<<<grid, 256, GEMM2_SMEM>>>(p_Ah, p_Al, p_Bh, p_Bl, b_hyp,
                                              p_t, nullptr, out, 0);
    }
}

// round 6
// speedup vs baseline: 2.1505x; 1.0207x over previous
#include <cuda_runtime.h>
#include <cuda_bf16.h>
#include <cstdint>
#include <cstddef>

#define BDIM   512
#define CELL   768
#define RANK   64
#define DF     256
#define KDNA   4000
#define NW     98304
#define HALF   49152
#define KSPLIT1 10

// GEMM2 tiling
#define KCH    32
#define NSTG   8                        // DF / KCH
#define LDA    56                       // A smem stride (bf16) -> 112B rows, conflict-free ldmatrix
#define LDB    132                      // B smem stride (fp32) -> conflict-free fragment LDS
#define A_BYTES (128 * LDA * 2)         // 14336
#define B_BYTES (KCH * LDB * 4)         // 16896
#define OFF_AH 0
#define OFF_AL (2 * A_BYTES)            // 28672
#define OFF_B  (4 * A_BYTES)            // 57344
#define GEMM2_SMEM (OFF_B + 2 * B_BYTES) // 91136

// ---------------------------------------------------------------------------
// asm helpers
// ---------------------------------------------------------------------------
__device__ __forceinline__ void mma_bf16(float c[4],
                                         uint32_t a0, uint32_t a1, uint32_t a2, uint32_t a3,
                                         uint32_t b0, uint32_t b1)
{
    asm volatile(
        "mma.sync.aligned.m16n8k16.row.col.f32.bf16.bf16.f32 "
        "{%0,%1,%2,%3}, {%4,%5,%6,%7}, {%8,%9}, {%0,%1,%2,%3};"
        : "+f"(c[0]), "+f"(c[1]), "+f"(c[2]), "+f"(c[3])
        : "r"(a0), "r"(a1), "r"(a2), "r"(a3), "r"(b0), "r"(b1));
}
__device__ __forceinline__ uint32_t smem_u32(const void* p) {
    uint32_t a;
    asm("{ .reg .u64 t; cvta.to.shared.u64 t, %1; cvt.u32.u64 %0, t; }" : "=r"(a) : "l"(p));
    return a;
}
#define LDMX4(r0, r1, r2, r3, addr) \
    asm volatile("ldmatrix.sync.aligned.m8n8.x4.shared.b16 {%0,%1,%2,%3}, [%4];" \
                 : "=r"(r0), "=r"(r1), "=r"(r2), "=r"(r3) : "r"(addr))
#define CP_ASYNC16(dst, src) \
    asm volatile("cp.async.cg.shared.global [%0], [%1], 16;" :: "r"(dst), "l"(src))
#define CP_COMMIT() asm volatile("cp.async.commit_group;" ::: "memory")
#define CP_WAIT1()  asm volatile("cp.async.wait_group 1;" ::: "memory")
#define CP_WAIT0()  asm volatile("cp.async.wait_group 0;" ::: "memory")

// split two fp32 (k-even, k-odd) into packed bf16x2 hi and lo fragments
__device__ __forceinline__ void bsplit(float fe, float fo, uint32_t& bh, uint32_t& bl) {
    __nv_bfloat162 h = __floats2bfloat162_rn(fe, fo);    // x = fe (low), y = fo
    float he = __bfloat162float(h.x);
    float ho = __bfloat162float(h.y);
    __nv_bfloat162 l = __floats2bfloat162_rn(fe - he, fo - ho);
    bh = *reinterpret_cast<uint32_t*>(&h);
    bl = *reinterpret_cast<uint32_t*>(&l);
}

// ---------------------------------------------------------------------------
// device scratch
// ---------------------------------------------------------------------------
__device__ float g_part[KSPLIT1 * BDIM * DF];
__device__ __align__(256) __nv_bfloat16 g_Ah[BDIM * DF];
__device__ __align__(256) __nv_bfloat16 g_Al[BDIM * DF];
__device__ float g_v[(size_t)BDIM * HALF];
__device__ float g_t[BDIM * RANK];

// ---------------------------------------------------------------------------
// GEMM1: SIMT 128x128x8 SGEMM, split-K partials
// ---------------------------------------------------------------------------
__global__ void __launch_bounds__(256, 2)
sgemm_k(const float* __restrict__ A, const float* __restrict__ Bmat,
        float* __restrict__ C, int M, int N, int K)
{
    const int bn = blockIdx.x, bm = blockIdx.y, slice = blockIdx.z;
    const int kPer = K / gridDim.z;
    const int k0base = slice * kPer;

    __shared__ float As[8][128];
    __shared__ float Bs[8][128];

    const int tid = threadIdx.x;
    const int aRow = tid >> 1, aK4 = (tid & 1) * 4;
    const int bK = tid >> 5, bN4 = (tid & 31) * 4;
    const int tx = tid & 15, ty = tid >> 4;

    float acc[8][8];
    #pragma unroll
    for (int i = 0; i < 8; i++)
        #pragma unroll
        for (int j = 0; j < 8; j++) acc[i][j] = 0.f;

    const float* Aptr = A + (size_t)(bm * 128 + aRow) * K + k0base + aK4;
    const float* Bptr = Bmat + (size_t)(k0base + bK) * N + (size_t)bn * 128 + bN4;

    const int nsteps = kPer / 8;
    for (int kt = 0; kt < nsteps; kt++) {
        float4 av = *(const float4*)(Aptr);
        float4 bv = *(const float4*)(Bptr);
        As[aK4 + 0][aRow] = av.x; As[aK4 + 1][aRow] = av.y;
        As[aK4 + 2][aRow] = av.z; As[aK4 + 3][aRow] = av.w;
        *(float4*)&Bs[bK][bN4] = bv;
        __syncthreads();
        #pragma unroll
        for (int k = 0; k < 8; k++) {
            float af[8], bf[8];
            #pragma unroll
            for (int i = 0; i < 8; i++) af[i] = As[k][ty * 8 + i];
            #pragma unroll
            for (int j = 0; j < 8; j++) bf[j] = Bs[k][tx * 8 + j];
            #pragma unroll
            for (int i = 0; i < 8; i++)
                #pragma unroll
                for (int j = 0; j < 8; j++) acc[i][j] += af[i] * bf[j];
        }
        __syncthreads();
        Aptr += 8;
        Bptr += (size_t)8 * N;
    }
    float* Cbase = C + (size_t)slice * M * N;
    #pragma unroll
    for (int i = 0; i < 8; i++) {
        const int row = bm * 128 + ty * 8 + i;
        #pragma unroll
        for (int j = 0; j < 8; j += 4) {
            const int col = bn * 128 + tx * 8 + j;
            float4 v = make_float4(acc[i][j], acc[i][j+1], acc[i][j+2], acc[i][j+3]);
            *(float4*)(Cbase + (size_t)row * N + col) = v;
        }
    }
}

// ---------------------------------------------------------------------------
// reduce split-K + bias + relu -> bf16 hi/lo split
// ---------------------------------------------------------------------------
__global__ void reduce_relu_convert_k(const float* __restrict__ part,
                                      const float* __restrict__ bias,
                                      __nv_bfloat16* __restrict__ Ah,
                                      __nv_bfloat16* __restrict__ Al)
{
    const int i = blockIdx.x * 256 + threadIdx.x;
    float s = bias[i & (DF - 1)];
    #pragma unroll
    for (int sl = 0; sl < KSPLIT1; sl++) s += part[sl * (BDIM * DF) + i];
    s = fmaxf(s, 0.f);
    __nv_bfloat16 h = __float2bfloat16(s);
    Ah[i] = h;
    Al[i] = __float2bfloat16(s - __bfloat162float(h));
}

// ---------------------------------------------------------------------------
// mma.sync GEMM, cp.async double-buffered, B read fp32 directly from W_hyper.
// C[128m x 128n] = A[128,256] @ W[:, n0:n0+128] with bf16x3 precision.
// V mode (pred==nullptr): writes C+bias to vout. U mode: contract with t -> pred.
// ---------------------------------------------------------------------------
__global__ void __launch_bounds__(256, 2)
gemm_mma_k(const __nv_bfloat16* __restrict__ Ahg, const __nv_bfloat16* __restrict__ Alg,
           const float* __restrict__ Wf, const float* __restrict__ bias,
           const float* __restrict__ tvec, float* __restrict__ vout,
           float* __restrict__ pred, int ntile0)
{
    extern __shared__ char smem[];
    const uint32_t sb = smem_u32(smem);
    const int tid = threadIdx.x, wid = tid >> 5, lane = tid & 31;
    const int bm = blockIdx.x;                 // fast dim -> W tile L2 reuse
    const int ntile = ntile0 + blockIdx.y;
    const int m0 = bm * 128, nrow0 = ntile * 128;
    const int warp_m = wid & 1, warp_n = wid >> 1;
    const int g = lane >> 2, t4 = lane & 3;

    float acc[4][4][4];
    #pragma unroll
    for (int mf = 0; mf < 4; mf++)
        #pragma unroll
        for (int nf = 0; nf < 4; nf++)
            #pragma unroll
            for (int c = 0; c < 4; c++) acc[mf][nf][c] = 0.f;

    const int a_row = warp_m * 64 + (lane & 15);
    const int a_koff = (lane >> 4) * 8;
    const int bq = lane & 3;                   // k quad within fragment
    const int bn_l = lane >> 2;                // n within 8-col fragment

    const __nv_bfloat16* Asrc_h = Ahg + (size_t)m0 * DF;
    const __nv_bfloat16* Asrc_l = Alg + (size_t)m0 * DF;

    auto load_stage = [&](int buf, int k0) {
        #pragma unroll
        for (int p = 0; p < 2; p++) {
            const int u = tid + p * 256;
            const int row = u >> 2, j = u & 3;
            const uint32_t so = (uint32_t)(row * LDA + j * 8) * 2;
            CP_ASYNC16(sb + OFF_AH + buf * A_BYTES + so,
                       Asrc_h + (size_t)row * DF + k0 + j * 8);
            CP_ASYNC16(sb + OFF_AL + buf * A_BYTES + so,
                       Asrc_l + (size_t)row * DF + k0 + j * 8);
        }
        #pragma unroll
        for (int p = 0; p < 4; p++) {
            const int u = tid + p * 256;
            const int row = u >> 5, c = u & 31;
            CP_ASYNC16(sb + OFF_B + buf * B_BYTES + (uint32_t)(row * LDB + c * 4) * 4,
                       Wf + (size_t)(k0 + row) * NW + nrow0 + c * 4);
        }
    };

    auto compute = [&](int buf) {
        const uint32_t ah_base = sb + OFF_AH + buf * A_BYTES;
        const uint32_t al_base = sb + OFF_AL + buf * A_BYTES;
        const float* sBf = (const float*)(smem + OFF_B + buf * B_BYTES);
        #pragma unroll
        for (int ks = 0; ks < 2; ks++) {
            uint32_t ah[4][4], al[4][4];
            #pragma unroll
            for (int mf = 0; mf < 4; mf++) {
                const uint32_t so = (uint32_t)((a_row + mf * 16) * LDA + ks * 16 + a_koff) * 2;
                LDMX4(ah[mf][0], ah[mf][1], ah[mf][2], ah[mf][3], ah_base + so);
                LDMX4(al[mf][0], al[mf][1], al[mf][2], al[mf][3], al_base + so);
            }
            #pragma unroll
            for (int nf = 0; nf < 4; nf++) {
                const int n = warp_n * 32 + nf * 8 + bn_l;
                const int kb = ks * 16 + 2 * bq;
                const float f00 = sBf[kb * LDB + n];
                const float f01 = sBf[(kb + 1) * LDB + n];
                const float f10 = sBf[(kb + 8) * LDB + n];
                const float f11 = sBf[(kb + 9) * LDB + n];
                uint32_t bh0, bl0, bh1, bl1;
                bsplit(f00, f01, bh0, bl0);
                bsplit(f10, f11, bh1, bl1);
                #pragma unroll
                for (int mf = 0; mf < 4; mf++)
                    mma_bf16(acc[mf][nf], ah[mf][0], ah[mf][1], ah[mf][2], ah[mf][3], bh0, bh1);
                #pragma unroll
                for (int mf = 0; mf < 4; mf++)
                    mma_bf16(acc[mf][nf], ah[mf][0], ah[mf][1], ah[mf][2], ah[mf][3], bl0, bl1);
                #pragma unroll
                for (int mf = 0; mf < 4; mf++)
                    mma_bf16(acc[mf][nf], al[mf][0], al[mf][1], al[mf][2], al[mf][3], bh0, bh1);
            }
        }
    };

    load_stage(0, 0);
    CP_COMMIT();
    for (int s = 0; s < NSTG; s++) {
        if (s + 1 < NSTG) {
            load_stage((s + 1) & 1, (s + 1) * KCH);
            CP_COMMIT();
            CP_WAIT1();
        } else {
            CP_WAIT0();
        }
        __syncthreads();
        compute(s & 1);
        __syncthreads();
    }

    // ------------------------- epilogue -------------------------
    if (pred == nullptr) {
        // V mode: direct stores of C + bias
        #pragma unroll
        for (int mf = 0; mf < 4; mf++) {
            const int row = warp_m * 64 + mf * 16 + g;
            #pragma unroll
            for (int nf = 0; nf < 4; nf++) {
                const int col = warp_n * 32 + nf * 8 + 2 * t4;
                const float b0 = bias[nrow0 + col], b1 = bias[nrow0 + col + 1];
                const size_t base = (size_t)(m0 + row) * HALF + (nrow0 - HALF) + col;
                float2 v0 = make_float2(acc[mf][nf][0] + b0, acc[mf][nf][1] + b1);
                float2 v1 = make_float2(acc[mf][nf][2] + b0, acc[mf][nf][3] + b1);
                *(float2*)&vout[base] = v0;
                *(float2*)&vout[base + (size_t)8 * HALF] = v1;
            }
        }
    } else {
        // U mode: pred[b, i] = sum_col (C+bias) * t[b, col&63]
        float* spart = (float*)smem;
        #pragma unroll
        for (int mf = 0; mf < 4; mf++) {
            const int row_lo = warp_m * 64 + mf * 16 + g;
            float p0 = 0.f, p1 = 0.f;
            #pragma unroll
            for (int nf = 0; nf < 4; nf++) {
                const int col = warp_n * 32 + nf * 8 + 2 * t4;
                const int r = col & 63;
                const float b0 = bias[nrow0 + col], b1 = bias[nrow0 + col + 1];
                const float* t0p = tvec + (size_t)(m0 + row_lo) * RANK;
                const float* t1p = tvec + (size_t)(m0 + row_lo + 8) * RANK;
                p0 += (acc[mf][nf][0] + b0) * t0p[r] + (acc[mf][nf][1] + b1) * t0p[r + 1];
                p1 += (acc[mf][nf][2] + b0) * t1p[r] + (acc[mf][nf][3] + b1) * t1p[r + 1];
            }
            p0 += __shfl_xor_sync(0xFFFFFFFF, p0, 1);
            p0 += __shfl_xor_sync(0xFFFFFFFF, p0, 2);
            p1 += __shfl_xor_sync(0xFFFFFFFF, p1, 1);
            p1 += __shfl_xor_sync(0xFFFFFFFF, p1, 2);
            if (t4 == 0) {
                spart[row_lo * 4 + warp_n] = p0;
                spart[(row_lo + 8) * 4 + warp_n] = p1;
            }
        }
        __syncthreads();
        {
            const int row = tid >> 1, ih = tid & 1;
            const float v = spart[row * 4 + 2 * ih] + spart[row * 4 + 2 * ih + 1];
            pred[(size_t)(m0 + row) * CELL + 2 * ntile + ih] = v;
        }
    }
}

// ---------------------------------------------------------------------------
// t[b,r] = sum_j V[b,j,r] * x[b,j]
// ---------------------------------------------------------------------------
__global__ void compute_t_k(const float* __restrict__ v, const float* __restrict__ x,
                            float* __restrict__ t)
{
    const int b = blockIdx.x;
    const int tid = threadIdx.x;
    const int r = tid & 63;
    const int jg = tid >> 6;
    __shared__ float sx[CELL];
    for (int j = tid; j < CELL; j += 256) sx[j] = x[(size_t)b * CELL + j];
    __syncthreads();
    const float* vb = v + (size_t)b * HALF;
    float acc = 0.f;
    for (int j = jg; j < CELL; j += 4)
        acc += vb[j * 64 + r] * sx[j];
    __shared__ float red[256];
    red[tid] = acc;
    __syncthreads();
    if (tid < 64)
        t[b * RANK + tid] = red[tid] + red[64 + tid] + red[128 + tid] + red[192 + tid];
}

// ---------------------------------------------------------------------------
// launch
// ---------------------------------------------------------------------------
extern "C" void kernel_launch(void* const* d_in, const int* in_sizes, int n_in,
                              void* d_out, int out_size)
{
    const float* x     = (const float*)d_in[0];
    const float* seq   = (const float*)d_in[1];
    const float* W_dna = (const float*)d_in[2];
    const float* b_dna = (const float*)d_in[3];
    const float* W_hyp = (const float*)d_in[4];
    const float* b_hyp = (const float*)d_in[5];
    float* out = (float*)d_out;

    float *p_part, *p_v, *p_t;
    __nv_bfloat16 *p_Ah, *p_Al;
    cudaGetSymbolAddress((void**)&p_part, g_part);
    cudaGetSymbolAddress((void**)&p_Ah, g_Ah);
    cudaGetSymbolAddress((void**)&p_Al, g_Al);
    cudaGetSymbolAddress((void**)&p_v, g_v);
    cudaGetSymbolAddress((void**)&p_t, g_t);

    cudaFuncSetAttribute(gemm_mma_k, cudaFuncAttributeMaxDynamicSharedMemorySize, GEMM2_SMEM);

    // GEMM1 split-K + epilogue (bias, relu, bf16 hi/lo)
    {
        dim3 grid(DF / 128, BDIM / 128, KSPLIT1);
        sgemm_k<<<grid, 256>>>(seq, W_dna, p_part, BDIM, DF, KDNA);
    }
    reduce_relu_convert_k<<<(BDIM * DF) / 256, 256>>>(p_part, b_dna, p_Ah, p_Al);

    // V-GEMM: n-tiles [384, 768) -> g_v (+bias)
    {
        dim3 grid(BDIM / 128, 384);
        gemm_mma_k<<<grid, 256, GEMM2_SMEM>>>(p_Ah, p_Al, W_hyp, b_hyp,
                                              nullptr, p_v, nullptr, 384);
    }
    // t = V^T x
    compute_t_k<<<BDIM, 256>>>(p_v, x, p_t);

    // U-GEMM: n-tiles [0, 384) fused with t-contraction -> out
    {
        dim3 grid(BDIM / 128, 384);
        gemm_mma_k<<<grid, 256, GEMM2_SMEM>>>(p_Ah, p_Al, W_hyp, b_hyp,
                                              p_t, nullptr, out, 0);
    }
}